// round 6
// baseline (speedup 1.0000x reference)
#include <cuda_runtime.h>
#include <cstddef>

// ContrastMemory for GB300 — row-inverted gather, copy fused into build.
// d_out layout (float32):
//   [0, H)          out_v1   = exp((memory_v2[idx] . v1)/T) / Z_v1
//   [H, 2H)         out_v2   = exp((memory_v1[idx] . v2)/T) / Z_v2
//   [2H, 2H+ND)     new_memory_v1
//   [2H+ND, 2H+2ND) new_memory_v2

#define T_INV 14.2857142857142857f   // 1/0.07
#define MOM   0.5f

#define MAX_N   100000
#define CAP     32
#define MAX_OVF 16384

// State invariant: d_count[0..N), d_ovf_cnt are ZERO at kernel_launch entry
// (zero-init at load; finish_kernel re-zeroes them). g_sum is zeroed by
// build_kernel before main_kernel accumulates.
__device__ int    d_count[MAX_N];
__device__ int    d_ell[(size_t)MAX_N * CAP];   // packed (b<<13)|k
__device__ int    d_ovf[MAX_OVF];
__device__ int    d_ovf_cnt;
__device__ double g_sum[2];                     // [0]: out_v1 raw sum, [1]: out_v2

// Counting-sort of the shared index set into ELL rows, fused with the
// memory-bank copy-through (DRAM stream overlaps atomic latency, and the
// bank reads warm L2 for main_kernel).
__global__ void __launch_bounds__(256) build_kernel(
        const int* __restrict__ idx, int H, int KP1, float invKP1,
        const float4* __restrict__ mem1,
        const float4* __restrict__ mem2,
        float4* __restrict__ outmem1,
        float4* __restrict__ outmem2,
        int NDv)   // N*D/4 float4 per bank
{
    const int tid      = blockIdx.x * blockDim.x + threadIdx.x;
    const int nthreads = gridDim.x * blockDim.x;

    if (tid == 0) { g_sum[0] = 0.0; g_sum[1] = 0.0; }

    // ---- ELL build ----
    if (tid < H) {
        const int r = __ldg(&idx[tid]);
        // b = tid / KP1 via float reciprocal + exact correction
        int b = __float2int_rz(__int2float_rn(tid) * invKP1);
        int k = tid - b * KP1;
        if (k < 0)         { b--; k += KP1; }
        else if (k >= KP1) { b++; k -= KP1; }

        const int packed = (b << 13) | k;
        const int pos = atomicAdd(&d_count[r], 1);
        if (pos < CAP) {
            d_ell[(size_t)r * CAP + pos] = packed;
        } else {
            const int o = atomicAdd(&d_ovf_cnt, 1);
            if (o < MAX_OVF) d_ovf[o] = packed;
        }
    }

    // ---- bank copy-through (reads fill L2; stores evict-first) ----
    for (int c = tid; c < NDv; c += nthreads) {
        const float4 a = mem1[c];
        const float4 b = mem2[c];
        __stcs(&outmem1[c], a);
        __stcs(&outmem2[c], b);
    }
}

// One warp per bank row: stage the row pair in shared, then process entries
// 4 at a time in 8-lane groups (3 SHFL stages reduce all 4 entries at once).
__global__ void __launch_bounds__(256) main_kernel(
        const float4* __restrict__ v1,
        const float4* __restrict__ v2,
        const int*    __restrict__ idx,
        const float4* __restrict__ mem1,
        const float4* __restrict__ mem2,
        float* __restrict__ out,
        int N, int H, int KP1)
{
    const int warpsPerBlock = blockDim.x >> 5;
    const int warpInBlock   = threadIdx.x >> 5;
    const int lane          = threadIdx.x & 31;
    const int g             = lane >> 3;   // entry group 0..3
    const int sl            = lane & 7;    // sub-lane within group
    const int gwarp         = blockIdx.x * warpsPerBlock + warpInBlock;
    const int totalWarps    = gridDim.x * warpsPerBlock;

    __shared__ float4 shm1[8][32];
    __shared__ float4 shm2[8][32];

    float local0 = 0.0f, local1 = 0.0f;

    for (int r = gwarp; r < N; r += totalWarps) {
        // stage row pair to shared (coalesced 512B x2, should hit L2)
        shm1[warpInBlock][lane] = mem1[(size_t)r * 32 + lane];
        shm2[warpInBlock][lane] = mem2[(size_t)r * 32 + lane];
        __syncwarp();

        const int cnt = min(d_count[r], CAP);
        for (int j = 0; j < cnt; j += 4) {
            const int e     = j + g;
            const bool valid = (e < cnt);
            const int eс    = valid ? e : (cnt - 1);
            const int p  = __ldg(&d_ell[(size_t)r * CAP + eс]);
            const int b  = p >> 13;
            const int d2 = b * KP1 + (p & 8191);

            float s1 = 0.0f, s2 = 0.0f;
            #pragma unroll
            for (int t = 0; t < 4; ++t) {
                const float4 m1 = shm1[warpInBlock][sl + 8 * t];
                const float4 m2 = shm2[warpInBlock][sl + 8 * t];
                const float4 x1 = __ldg(&v1[(size_t)b * 32 + sl + 8 * t]);
                const float4 x2 = __ldg(&v2[(size_t)b * 32 + sl + 8 * t]);
                s1 += m1.x * x2.x + m1.y * x2.y + m1.z * x2.z + m1.w * x2.w; // -> out_v2
                s2 += m2.x * x1.x + m2.y * x1.y + m2.z * x1.z + m2.w * x1.w; // -> out_v1
            }
            // reduce within 8-lane groups: all 4 entries at once
            s1 += __shfl_xor_sync(0xffffffffu, s1, 1);
            s2 += __shfl_xor_sync(0xffffffffu, s2, 1);
            s1 += __shfl_xor_sync(0xffffffffu, s1, 2);
            s2 += __shfl_xor_sync(0xffffffffu, s2, 2);
            s1 += __shfl_xor_sync(0xffffffffu, s1, 4);
            s2 += __shfl_xor_sync(0xffffffffu, s2, 4);

            if (sl == 0 && valid) {
                const float e2 = __expf(s2 * T_INV);   // out_v1
                const float e1 = __expf(s1 * T_INV);   // out_v2
                __stcs(&out[d2], e2);
                __stcs(&out[H + d2], e1);
                local0 += e2;
                local1 += e1;
            }
        }
        __syncwarp();   // protect shared before next row overwrite
    }

    // overflow entries (expected: none) — direct gather path, one warp each
    const int novf = min(d_ovf_cnt, MAX_OVF);
    for (int o = gwarp; o < novf; o += totalWarps) {
        const int p  = d_ovf[o];
        const int b  = p >> 13;
        const int d2 = b * KP1 + (p & 8191);
        const int r  = __ldg(&idx[d2]);

        const float4 m1 = mem1[(size_t)r * 32 + lane];
        const float4 m2 = mem2[(size_t)r * 32 + lane];
        const float4 x1 = __ldg(&v1[(size_t)b * 32 + lane]);
        const float4 x2 = __ldg(&v2[(size_t)b * 32 + lane]);

        float s1 = m1.x * x2.x + m1.y * x2.y + m1.z * x2.z + m1.w * x2.w;
        float s2 = m2.x * x1.x + m2.y * x1.y + m2.z * x1.z + m2.w * x1.w;
        #pragma unroll
        for (int q = 16; q > 0; q >>= 1) {
            s1 += __shfl_xor_sync(0xffffffffu, s1, q);
            s2 += __shfl_xor_sync(0xffffffffu, s2, q);
        }
        if (lane == 0) {
            const float e2 = __expf(s2 * T_INV);
            const float e1 = __expf(s1 * T_INV);
            __stcs(&out[d2], e2);
            __stcs(&out[H + d2], e1);
            local0 += e2;
            local1 += e1;
        }
    }

    // block reduce -> one double atomic per block per half
    #pragma unroll
    for (int o = 16; o > 0; o >>= 1) {
        local0 += __shfl_xor_sync(0xffffffffu, local0, o);
        local1 += __shfl_xor_sync(0xffffffffu, local1, o);
    }
    __shared__ float sh0[8], sh1[8];
    if (lane == 0) { sh0[warpInBlock] = local0; sh1[warpInBlock] = local1; }
    __syncthreads();
    if (threadIdx.x == 0) {
        float a = 0.0f, b = 0.0f;
        for (int w = 0; w < warpsPerBlock; ++w) { a += sh0[w]; b += sh1[w]; }
        atomicAdd(&g_sum[0], (double)a);
        atomicAdd(&g_sum[1], (double)b);
    }
}

// Epilogue: scale score halves by 1/Z, momentum-update the B rows, and restore
// the zero-state invariant (counts, overflow counter).
__global__ void __launch_bounds__(256) finish_kernel(
        float4* __restrict__ out4,
        int Hv2,   // 2H/4
        int Hv,    // H/4
        int H, long long Nll, int N,
        const float* __restrict__ v1,
        const float* __restrict__ v2,
        const float* __restrict__ mem1,
        const float* __restrict__ mem2,
        const int*   __restrict__ y,
        float* __restrict__ outmem1,
        float* __restrict__ outmem2,
        int scaleBlocks, int B)
{
    const int bx = (int)blockIdx.x;

    if (bx < scaleBlocks) {
        const int i = bx * blockDim.x + threadIdx.x;
        if (i < Hv2) {
            const double s = (i < Hv) ? g_sum[0] : g_sum[1];
            const float scale = (float)((double)H / (s * (double)Nll));
            float4 v = out4[i];
            v.x *= scale; v.y *= scale; v.z *= scale; v.w *= scale;
            out4[i] = v;
        }
        return;
    }

    if (bx < scaleBlocks + B) {
        // momentum update: 2 (row, view) pairs per block
        const int ub    = bx - scaleBlocks;
        const int which = threadIdx.x >> 7;
        const int t     = threadIdx.x & 127;
        const int lane  = threadIdx.x & 31;
        const int w128  = (threadIdx.x >> 5) & 3;

        const float* v      = which ? v2      : v1;
        const float* mem    = which ? mem2    : mem1;
        float*       outmem = which ? outmem2 : outmem1;

        const int row = __ldg(&y[ub]);
        const float u = MOM * mem[(size_t)row * 128 + t] + (1.0f - MOM) * v[(size_t)ub * 128 + t];

        float ss = u * u;
        #pragma unroll
        for (int o = 16; o > 0; o >>= 1)
            ss += __shfl_xor_sync(0xffffffffu, ss, o);

        __shared__ float sh[2][4];
        if (lane == 0) sh[which][w128] = ss;
        __syncthreads();

        const float tot = sh[which][0] + sh[which][1] + sh[which][2] + sh[which][3];
        outmem[(size_t)row * 128 + t] = u * rsqrtf(tot);
        return;
    }

    // zero-state restore (d_count, d_ovf_cnt not read in this kernel)
    const int zb = bx - scaleBlocks - B;
    const int i  = zb * blockDim.x + threadIdx.x;
    if (i < N) d_count[i] = 0;
    if (i == 0) d_ovf_cnt = 0;
}

extern "C" void kernel_launch(void* const* d_in, const int* in_sizes, int n_in,
                              void* d_out, int out_size)
{
    const float* v1   = (const float*)d_in[0];
    const float* v2   = (const float*)d_in[1];
    const int*   idx  = (const int*)  d_in[2];
    const int*   y    = (const int*)  d_in[3];
    const float* mem1 = (const float*)d_in[4];
    const float* mem2 = (const float*)d_in[5];

    const int B   = in_sizes[3];          // 128
    const int D   = in_sizes[0] / B;      // 128
    const int KP1 = in_sizes[2] / B;      // 4097
    const int N   = in_sizes[4] / D;      // 100000
    const int H   = B * KP1;              // 524416
    const int ND  = N * D;                // 12800000
    const int NDv = ND / 4;

    float* out = (float*)d_out;
    float* outmem1 = out + 2 * (size_t)H;
    float* outmem2 = outmem1 + (size_t)ND;

    const float invKP1 = 1.0f / (float)KP1;

    build_kernel<<<(H + 255) / 256, 256>>>(idx, H, KP1, invKP1,
                                           (const float4*)mem1, (const float4*)mem2,
                                           (float4*)outmem1, (float4*)outmem2, NDv);

    main_kernel<<<1998, 256>>>((const float4*)v1, (const float4*)v2, idx,
                               (const float4*)mem1, (const float4*)mem2,
                               out, N, H, KP1);

    const int Hv  = H / 4;
    const int Hv2 = 2 * Hv;
    const int scaleBlocks = (Hv2 + 255) / 256;
    const int zeroBlocks  = (N + 255) / 256;
    finish_kernel<<<scaleBlocks + B + zeroBlocks, 256>>>(
        (float4*)d_out, Hv2, Hv, H, (long long)N, N,
        v1, v2, mem1, mem2, y, outmem1, outmem2, scaleBlocks, B);
}

// round 7
// speedup vs baseline: 1.2152x; 1.2152x over previous
#include <cuda_runtime.h>
#include <cstddef>

// ContrastMemory for GB300 — row-inverted gather; copy fused into main
// (each bank row is read from DRAM exactly once, serving copy + all dots).
// d_out layout (float32):
//   [0, H)          out_v1   = exp((memory_v2[idx] . v1)/T) / Z_v1
//   [H, 2H)         out_v2   = exp((memory_v1[idx] . v2)/T) / Z_v2
//   [2H, 2H+ND)     new_memory_v1
//   [2H+ND, 2H+2ND) new_memory_v2

#define T_INV 14.2857142857142857f   // 1/0.07
#define MOM   0.5f

#define MAX_N   100000
#define CAP     32
#define MAX_OVF 16384

// State invariant: d_count[0..N), d_ovf_cnt are ZERO at kernel_launch entry
// (zero-init at load; finish_kernel re-zeroes them). g_sum is zeroed by
// build_kernel before main_kernel accumulates.
__device__ int    d_count[MAX_N];
__device__ int    d_ell[(size_t)MAX_N * CAP];   // packed (b<<13)|k
__device__ int    d_ovf[MAX_OVF];
__device__ int    d_ovf_cnt;
__device__ double g_sum[2];                     // [0]: out_v1 raw sum, [1]: out_v2

// Counting-sort of the shared index set into ELL rows (small, ~10 us).
__global__ void __launch_bounds__(256) build_kernel(
        const int* __restrict__ idx, int H, int KP1, float invKP1)
{
    const int i = blockIdx.x * blockDim.x + threadIdx.x;
    if (i == 0) { g_sum[0] = 0.0; g_sum[1] = 0.0; }
    if (i >= H) return;

    const int r = __ldg(&idx[i]);
    // b = i / KP1 via float reciprocal + exact correction
    int b = __float2int_rz(__int2float_rn(i) * invKP1);
    int k = i - b * KP1;
    if (k < 0)         { b--; k += KP1; }
    else if (k >= KP1) { b++; k -= KP1; }

    const int packed = (b << 13) | k;
    const int pos = atomicAdd(&d_count[r], 1);
    if (pos < CAP) {
        d_ell[(size_t)r * CAP + pos] = packed;
    } else {
        const int o = atomicAdd(&d_ovf_cnt, 1);
        if (o < MAX_OVF) d_ovf[o] = packed;
    }
}

// One warp per bank row: load mem1[r]+mem2[r] once (DRAM), copy them out,
// stage in shared, then process ELL entries 4 at a time in 8-lane groups.
__global__ void __launch_bounds__(256) main_kernel(
        const float4* __restrict__ v1,
        const float4* __restrict__ v2,
        const int*    __restrict__ idx,
        const float4* __restrict__ mem1,
        const float4* __restrict__ mem2,
        float* __restrict__ out,
        float4* __restrict__ outmem1,
        float4* __restrict__ outmem2,
        int N, int H, int KP1)
{
    const int warpsPerBlock = blockDim.x >> 5;
    const int warpInBlock   = threadIdx.x >> 5;
    const int lane          = threadIdx.x & 31;
    const int g             = lane >> 3;   // entry slot within quad (0..3)
    const int sl            = lane & 7;    // sub-lane within 8-lane group
    const int gwarp         = blockIdx.x * warpsPerBlock + warpInBlock;
    const int totalWarps    = gridDim.x * warpsPerBlock;

    __shared__ float4 shm1[8][32];
    __shared__ float4 shm2[8][32];

    float local0 = 0.0f, local1 = 0.0f;

    for (int r = gwarp; r < N; r += totalWarps) {
        // single DRAM read of the row pair; serves copy AND all dots
        const float4 m1 = mem1[(size_t)r * 32 + lane];
        const float4 m2 = mem2[(size_t)r * 32 + lane];

        // copy-through (evict-first stores)
        __stcs(&outmem1[(size_t)r * 32 + lane], m1);
        __stcs(&outmem2[(size_t)r * 32 + lane], m2);

        const int cnt = min(d_count[r], CAP);
        if (cnt == 0) continue;

        shm1[warpInBlock][lane] = m1;
        shm2[warpInBlock][lane] = m2;
        __syncwarp();

        for (int j = 0; j < cnt; j += 4) {
            const int  e     = j + g;
            const bool valid = (e < cnt);
            const int  ec    = valid ? e : (cnt - 1);
            const int  p     = __ldg(&d_ell[(size_t)r * CAP + ec]);
            const int  b     = p >> 13;
            const int  d2    = b * KP1 + (p & 8191);

            float s1 = 0.0f, s2 = 0.0f;
            #pragma unroll
            for (int t = 0; t < 4; ++t) {
                const float4 a1 = shm1[warpInBlock][sl + 8 * t];
                const float4 a2 = shm2[warpInBlock][sl + 8 * t];
                const float4 x1 = __ldg(&v1[(size_t)b * 32 + sl + 8 * t]);
                const float4 x2 = __ldg(&v2[(size_t)b * 32 + sl + 8 * t]);
                s1 += a1.x * x2.x + a1.y * x2.y + a1.z * x2.z + a1.w * x2.w; // -> out_v2
                s2 += a2.x * x1.x + a2.y * x1.y + a2.z * x1.z + a2.w * x1.w; // -> out_v1
            }
            // reduce within 8-lane groups: 4 entries reduced by 6 shuffles
            s1 += __shfl_xor_sync(0xffffffffu, s1, 1);
            s2 += __shfl_xor_sync(0xffffffffu, s2, 1);
            s1 += __shfl_xor_sync(0xffffffffu, s1, 2);
            s2 += __shfl_xor_sync(0xffffffffu, s2, 2);
            s1 += __shfl_xor_sync(0xffffffffu, s1, 4);
            s2 += __shfl_xor_sync(0xffffffffu, s2, 4);

            if (sl == 0 && valid) {
                const float e2 = __expf(s2 * T_INV);   // out_v1
                const float e1 = __expf(s1 * T_INV);   // out_v2
                __stcs(&out[d2], e2);
                __stcs(&out[H + d2], e1);
                local0 += e2;
                local1 += e1;
            }
        }
        __syncwarp();   // protect shared before next row overwrites it
    }

    // overflow entries (expected: none) — direct full-warp gather path
    const int novf = min(d_ovf_cnt, MAX_OVF);
    for (int o = gwarp; o < novf; o += totalWarps) {
        const int p  = d_ovf[o];
        const int b  = p >> 13;
        const int d2 = b * KP1 + (p & 8191);
        const int r  = __ldg(&idx[d2]);

        const float4 m1 = mem1[(size_t)r * 32 + lane];
        const float4 m2 = mem2[(size_t)r * 32 + lane];
        const float4 x1 = __ldg(&v1[(size_t)b * 32 + lane]);
        const float4 x2 = __ldg(&v2[(size_t)b * 32 + lane]);

        float s1 = m1.x * x2.x + m1.y * x2.y + m1.z * x2.z + m1.w * x2.w;
        float s2 = m2.x * x1.x + m2.y * x1.y + m2.z * x1.z + m2.w * x1.w;
        #pragma unroll
        for (int q = 16; q > 0; q >>= 1) {
            s1 += __shfl_xor_sync(0xffffffffu, s1, q);
            s2 += __shfl_xor_sync(0xffffffffu, s2, q);
        }
        if (lane == 0) {
            const float e2 = __expf(s2 * T_INV);
            const float e1 = __expf(s1 * T_INV);
            __stcs(&out[d2], e2);
            __stcs(&out[H + d2], e1);
            local0 += e2;
            local1 += e1;
        }
    }

    // block reduce -> one double atomic per block per half
    #pragma unroll
    for (int o = 16; o > 0; o >>= 1) {
        local0 += __shfl_xor_sync(0xffffffffu, local0, o);
        local1 += __shfl_xor_sync(0xffffffffu, local1, o);
    }
    __shared__ float sh0[8], sh1[8];
    if (lane == 0) { sh0[warpInBlock] = local0; sh1[warpInBlock] = local1; }
    __syncthreads();
    if (threadIdx.x == 0) {
        float a = 0.0f, b = 0.0f;
        for (int w = 0; w < warpsPerBlock; ++w) { a += sh0[w]; b += sh1[w]; }
        atomicAdd(&g_sum[0], (double)a);
        atomicAdd(&g_sum[1], (double)b);
    }
}

// Epilogue: scale score halves by 1/Z, momentum-update the B rows, and restore
// the zero-state invariant (counts, overflow counter).
__global__ void __launch_bounds__(256) finish_kernel(
        float4* __restrict__ out4,
        int Hv2,   // 2H/4
        int Hv,    // H/4
        int H, long long Nll, int N,
        const float* __restrict__ v1,
        const float* __restrict__ v2,
        const float* __restrict__ mem1,
        const float* __restrict__ mem2,
        const int*   __restrict__ y,
        float* __restrict__ outmem1,
        float* __restrict__ outmem2,
        int scaleBlocks, int B)
{
    const int bx = (int)blockIdx.x;

    if (bx < scaleBlocks) {
        const int i = bx * blockDim.x + threadIdx.x;
        if (i < Hv2) {
            const double s = (i < Hv) ? g_sum[0] : g_sum[1];
            const float scale = (float)((double)H / (s * (double)Nll));
            float4 v = out4[i];
            v.x *= scale; v.y *= scale; v.z *= scale; v.w *= scale;
            out4[i] = v;
        }
        return;
    }

    if (bx < scaleBlocks + B) {
        // momentum update: 2 (row, view) pairs per block
        const int ub    = bx - scaleBlocks;
        const int which = threadIdx.x >> 7;
        const int t     = threadIdx.x & 127;
        const int lane  = threadIdx.x & 31;
        const int w128  = (threadIdx.x >> 5) & 3;

        const float* v      = which ? v2      : v1;
        const float* mem    = which ? mem2    : mem1;
        float*       outmem = which ? outmem2 : outmem1;

        const int row = __ldg(&y[ub]);
        const float u = MOM * mem[(size_t)row * 128 + t] + (1.0f - MOM) * v[(size_t)ub * 128 + t];

        float ss = u * u;
        #pragma unroll
        for (int o = 16; o > 0; o >>= 1)
            ss += __shfl_xor_sync(0xffffffffu, ss, o);

        __shared__ float sh[2][4];
        if (lane == 0) sh[which][w128] = ss;
        __syncthreads();

        const float tot = sh[which][0] + sh[which][1] + sh[which][2] + sh[which][3];
        outmem[(size_t)row * 128 + t] = u * rsqrtf(tot);
        return;
    }

    // zero-state restore (d_count, d_ovf_cnt not read in this kernel)
    const int zb = bx - scaleBlocks - B;
    const int i  = zb * blockDim.x + threadIdx.x;
    if (i < N) d_count[i] = 0;
    if (i == 0) d_ovf_cnt = 0;
}

extern "C" void kernel_launch(void* const* d_in, const int* in_sizes, int n_in,
                              void* d_out, int out_size)
{
    const float* v1   = (const float*)d_in[0];
    const float* v2   = (const float*)d_in[1];
    const int*   idx  = (const int*)  d_in[2];
    const int*   y    = (const int*)  d_in[3];
    const float* mem1 = (const float*)d_in[4];
    const float* mem2 = (const float*)d_in[5];

    const int B   = in_sizes[3];          // 128
    const int D   = in_sizes[0] / B;      // 128
    const int KP1 = in_sizes[2] / B;      // 4097
    const int N   = in_sizes[4] / D;      // 100000
    const int H   = B * KP1;              // 524416
    const int ND  = N * D;                // 12800000

    float* out = (float*)d_out;
    float* outmem1 = out + 2 * (size_t)H;
    float* outmem2 = outmem1 + (size_t)ND;

    const float invKP1 = 1.0f / (float)KP1;

    build_kernel<<<(H + 255) / 256, 256>>>(idx, H, KP1, invKP1);

    main_kernel<<<1998, 256>>>((const float4*)v1, (const float4*)v2, idx,
                               (const float4*)mem1, (const float4*)mem2,
                               out, (float4*)outmem1, (float4*)outmem2,
                               N, H, KP1);

    const int Hv  = H / 4;
    const int Hv2 = 2 * Hv;
    const int scaleBlocks = (Hv2 + 255) / 256;
    const int zeroBlocks  = (N + 255) / 256;
    finish_kernel<<<scaleBlocks + B + zeroBlocks, 256>>>(
        (float4*)d_out, Hv2, Hv, H, (long long)N, N,
        v1, v2, mem1, mem2, y, outmem1, outmem2, scaleBlocks, B);
}

// round 9
// speedup vs baseline: 1.3228x; 1.0885x over previous
#include <cuda_runtime.h>
#include <cstddef>

// ContrastMemory for GB300 — row-inverted gather; copy fused into main
// (each bank row is read from DRAM exactly once, serving copy + all dots).
// Main is software-pipelined: next row pair's loads are issued before the
// current row's entry loop.
// d_out layout (float32):
//   [0, H)          out_v1   = exp((memory_v2[idx] . v1)/T) / Z_v1
//   [H, 2H)         out_v2   = exp((memory_v1[idx] . v2)/T) / Z_v2
//   [2H, 2H+ND)     new_memory_v1
//   [2H+ND, 2H+2ND) new_memory_v2

#define T_INV 14.2857142857142857f   // 1/0.07
#define MOM   0.5f

#define MAX_N   100000
#define CAP     32
#define MAX_OVF 16384

// State invariant: d_count[0..N), d_ovf_cnt are ZERO at kernel_launch entry
// (zero-init at load; finish_kernel re-zeroes them). g_sum is zeroed by
// build_kernel before main_kernel accumulates.
__device__ int    d_count[MAX_N];
__device__ int    d_ell[(size_t)MAX_N * CAP];   // packed (b<<13)|k
__device__ int    d_ovf[MAX_OVF];
__device__ int    d_ovf_cnt;
__device__ double g_sum[2];                     // [0]: out_v1 raw sum, [1]: out_v2

// Counting-sort of the shared index set into ELL rows (~10 us, atomic-bound).
__global__ void __launch_bounds__(256) build_kernel(
        const int* __restrict__ idx, int H, int KP1, float invKP1)
{
    const int i = blockIdx.x * blockDim.x + threadIdx.x;
    if (i == 0) { g_sum[0] = 0.0; g_sum[1] = 0.0; }
    if (i >= H) return;

    const int r = __ldg(&idx[i]);
    // b = i / KP1 via float reciprocal + exact correction
    int b = __float2int_rz(__int2float_rn(i) * invKP1);
    int k = i - b * KP1;
    if (k < 0)         { b--; k += KP1; }
    else if (k >= KP1) { b++; k -= KP1; }

    const int packed = (b << 13) | k;
    const int pos = atomicAdd(&d_count[r], 1);
    if (pos < CAP) {
        d_ell[(size_t)r * CAP + pos] = packed;
    } else {
        const int o = atomicAdd(&d_ovf_cnt, 1);
        if (o < MAX_OVF) d_ovf[o] = packed;
    }
}

// One warp per bank row; rows held in registers; next row prefetched before
// the current row's entry loop (double per-warp DRAM MLP).
__global__ void __launch_bounds__(256) main_kernel(
        const float4* __restrict__ v1,
        const float4* __restrict__ v2,
        const int*    __restrict__ idx,
        const float4* __restrict__ mem1,
        const float4* __restrict__ mem2,
        float* __restrict__ out,
        float4* __restrict__ outmem1,
        float4* __restrict__ outmem2,
        int N, int H, int KP1)
{
    const int warpsPerBlock = blockDim.x >> 5;
    const int warpInBlock   = threadIdx.x >> 5;
    const int lane          = threadIdx.x & 31;
    const int gwarp         = blockIdx.x * warpsPerBlock + warpInBlock;
    const int totalWarps    = gridDim.x * warpsPerBlock;

    float local0 = 0.0f, local1 = 0.0f;

    int r = gwarp;
    float4 m1, m2;
    int cnt = 0;
    if (r < N) {
        m1  = mem1[(size_t)r * 32 + lane];
        m2  = mem2[(size_t)r * 32 + lane];
        cnt = min(d_count[r], CAP);
    }

    while (r < N) {
        const int rn = r + totalWarps;

        // prefetch next row pair + count (DRAM latency hidden by entry loop)
        float4 m1n, m2n;
        int cntn = 0;
        if (rn < N) {
            m1n  = mem1[(size_t)rn * 32 + lane];
            m2n  = mem2[(size_t)rn * 32 + lane];
            cntn = min(d_count[rn], CAP);
        }

        // copy-through of current row (evict-first stores)
        __stcs(&outmem1[(size_t)r * 32 + lane], m1);
        __stcs(&outmem2[(size_t)r * 32 + lane], m2);

        // entry loop for current row
        for (int j = 0; j < cnt; ++j) {
            const int p  = __ldg(&d_ell[(size_t)r * CAP + j]);
            const int b  = p >> 13;
            const int d2 = b * KP1 + (p & 8191);

            const float4 x1 = __ldg(&v1[(size_t)b * 32 + lane]);  // L1-resident
            const float4 x2 = __ldg(&v2[(size_t)b * 32 + lane]);

            float s1 = m1.x * x2.x + m1.y * x2.y + m1.z * x2.z + m1.w * x2.w; // -> out_v2
            float s2 = m2.x * x1.x + m2.y * x1.y + m2.z * x1.z + m2.w * x1.w; // -> out_v1

            #pragma unroll
            for (int o = 16; o > 0; o >>= 1) {
                s1 += __shfl_xor_sync(0xffffffffu, s1, o);
                s2 += __shfl_xor_sync(0xffffffffu, s2, o);
            }

            if (lane == 0) {
                const float e2 = __expf(s2 * T_INV);   // out_v1
                const float e1 = __expf(s1 * T_INV);   // out_v2
                __stcs(&out[d2], e2);
                __stcs(&out[H + d2], e1);
                local0 += e2;
                local1 += e1;
            }
        }

        m1 = m1n; m2 = m2n; cnt = cntn; r = rn;
    }

    // overflow entries (expected: none) — direct full-warp gather path
    const int novf = min(d_ovf_cnt, MAX_OVF);
    for (int o = gwarp; o < novf; o += totalWarps) {
        const int p  = d_ovf[o];
        const int b  = p >> 13;
        const int d2 = b * KP1 + (p & 8191);
        const int rr = __ldg(&idx[d2]);

        const float4 a1 = mem1[(size_t)rr * 32 + lane];
        const float4 a2 = mem2[(size_t)rr * 32 + lane];
        const float4 x1 = __ldg(&v1[(size_t)b * 32 + lane]);
        const float4 x2 = __ldg(&v2[(size_t)b * 32 + lane]);

        float s1 = a1.x * x2.x + a1.y * x2.y + a1.z * x2.z + a1.w * x2.w;
        float s2 = a2.x * x1.x + a2.y * x1.y + a2.z * x1.z + a2.w * x1.w;
        #pragma unroll
        for (int q = 16; q > 0; q >>= 1) {
            s1 += __shfl_xor_sync(0xffffffffu, s1, q);
            s2 += __shfl_xor_sync(0xffffffffu, s2, q);
        }
        if (lane == 0) {
            const float e2 = __expf(s2 * T_INV);
            const float e1 = __expf(s1 * T_INV);
            __stcs(&out[d2], e2);
            __stcs(&out[H + d2], e1);
            local0 += e2;
            local1 += e1;
        }
    }

    // block reduce -> one double atomic per block per half
    #pragma unroll
    for (int o = 16; o > 0; o >>= 1) {
        local0 += __shfl_xor_sync(0xffffffffu, local0, o);
        local1 += __shfl_xor_sync(0xffffffffu, local1, o);
    }
    __shared__ float sh0[8], sh1[8];
    if (lane == 0) { sh0[warpInBlock] = local0; sh1[warpInBlock] = local1; }
    __syncthreads();
    if (threadIdx.x == 0) {
        float a = 0.0f, b = 0.0f;
        for (int w = 0; w < warpsPerBlock; ++w) { a += sh0[w]; b += sh1[w]; }
        atomicAdd(&g_sum[0], (double)a);
        atomicAdd(&g_sum[1], (double)b);
    }
}

// Epilogue: scale score halves by 1/Z, momentum-update the B rows, and restore
// the zero-state invariant (counts, overflow counter).
__global__ void __launch_bounds__(256) finish_kernel(
        float4* __restrict__ out4,
        int Hv2,   // 2H/4
        int Hv,    // H/4
        int H, long long Nll, int N,
        const float* __restrict__ v1,
        const float* __restrict__ v2,
        const float* __restrict__ mem1,
        const float* __restrict__ mem2,
        const int*   __restrict__ y,
        float* __restrict__ outmem1,
        float* __restrict__ outmem2,
        int scaleBlocks, int B)
{
    const int bx = (int)blockIdx.x;

    if (bx < scaleBlocks) {
        const int i = bx * blockDim.x + threadIdx.x;
        if (i < Hv2) {
            const double s = (i < Hv) ? g_sum[0] : g_sum[1];
            const float scale = (float)((double)H / (s * (double)Nll));
            float4 v = out4[i];
            v.x *= scale; v.y *= scale; v.z *= scale; v.w *= scale;
            out4[i] = v;
        }
        return;
    }

    if (bx < scaleBlocks + B) {
        // momentum update: 2 (row, view) pairs per block
        const int ub    = bx - scaleBlocks;
        const int which = threadIdx.x >> 7;
        const int t     = threadIdx.x & 127;
        const int lane  = threadIdx.x & 31;
        const int w128  = (threadIdx.x >> 5) & 3;

        const float* v      = which ? v2      : v1;
        const float* mem    = which ? mem2    : mem1;
        float*       outmem = which ? outmem2 : outmem1;

        const int row = __ldg(&y[ub]);
        const float u = MOM * mem[(size_t)row * 128 + t] + (1.0f - MOM) * v[(size_t)ub * 128 + t];

        float ss = u * u;
        #pragma unroll
        for (int o = 16; o > 0; o >>= 1)
            ss += __shfl_xor_sync(0xffffffffu, ss, o);

        __shared__ float sh[2][4];
        if (lane == 0) sh[which][w128] = ss;
        __syncthreads();

        const float tot = sh[which][0] + sh[which][1] + sh[which][2] + sh[which][3];
        outmem[(size_t)row * 128 + t] = u * rsqrtf(tot);
        return;
    }

    // zero-state restore (d_count, d_ovf_cnt not read in this kernel)
    const int zb = bx - scaleBlocks - B;
    const int i  = zb * blockDim.x + threadIdx.x;
    if (i < N) d_count[i] = 0;
    if (i == 0) d_ovf_cnt = 0;
}

extern "C" void kernel_launch(void* const* d_in, const int* in_sizes, int n_in,
                              void* d_out, int out_size)
{
    const float* v1   = (const float*)d_in[0];
    const float* v2   = (const float*)d_in[1];
    const int*   idx  = (const int*)  d_in[2];
    const int*   y    = (const int*)  d_in[3];
    const float* mem1 = (const float*)d_in[4];
    const float* mem2 = (const float*)d_in[5];

    const int B   = in_sizes[3];          // 128
    const int D   = in_sizes[0] / B;      // 128
    const int KP1 = in_sizes[2] / B;      // 4097
    const int N   = in_sizes[4] / D;      // 100000
    const int H   = B * KP1;              // 524416
    const int ND  = N * D;                // 12800000

    float* out = (float*)d_out;
    float* outmem1 = out + 2 * (size_t)H;
    float* outmem2 = outmem1 + (size_t)ND;

    const float invKP1 = 1.0f / (float)KP1;

    build_kernel<<<(H + 255) / 256, 256>>>(idx, H, KP1, invKP1);

    main_kernel<<<1998, 256>>>((const float4*)v1, (const float4*)v2, idx,
                               (const float4*)mem1, (const float4*)mem2,
                               out, (float4*)outmem1, (float4*)outmem2,
                               N, H, KP1);

    const int Hv  = H / 4;
    const int Hv2 = 2 * Hv;
    const int scaleBlocks = (Hv2 + 255) / 256;
    const int zeroBlocks  = (N + 255) / 256;
    finish_kernel<<<scaleBlocks + B + zeroBlocks, 256>>>(
        (float4*)d_out, Hv2, Hv, H, (long long)N, N,
        v1, v2, mem1, mem2, y, outmem1, outmem2, scaleBlocks, B);
}

// round 10
// speedup vs baseline: 1.3773x; 1.0412x over previous
#include <cuda_runtime.h>
#include <cstddef>

// ContrastMemory for GB300 — row-inverted gather; copy fused into main.
// Main uses a batched 8-value pack-and-butterfly warp reduction:
// 4 entries x 2 views reduced with 16 SHFLs, results land in 8 lanes
// (parallel expf, 2 scattered-store instructions per 4 entries).
// d_out layout (float32):
//   [0, H)          out_v1   = exp((memory_v2[idx] . v1)/T) / Z_v1
//   [H, 2H)         out_v2   = exp((memory_v1[idx] . v2)/T) / Z_v2
//   [2H, 2H+ND)     new_memory_v1
//   [2H+ND, 2H+2ND) new_memory_v2

#define T_INV 14.2857142857142857f   // 1/0.07
#define MOM   0.5f

#define MAX_N   100000
#define CAP     32
#define MAX_OVF 16384

// State invariant: d_count[0..N), d_ovf_cnt are ZERO at kernel_launch entry
// (zero-init at load; finish_kernel re-zeroes them). g_sum is zeroed by
// build_kernel before main_kernel accumulates. d_ell slots >= cnt are either
// zero (first run) or stale-but-identical (replays) — never stored from.
__device__ int    d_count[MAX_N];
__device__ int    d_ell[(size_t)MAX_N * CAP];   // packed (b<<13)|k ; row stride 128B (int4-aligned)
__device__ int    d_ovf[MAX_OVF];
__device__ int    d_ovf_cnt;
__device__ double g_sum[2];                     // [0]: out_v1 raw sum, [1]: out_v2

// Counting-sort of the shared index set into ELL rows (~10 us, atomic-bound).
__global__ void __launch_bounds__(256) build_kernel(
        const int* __restrict__ idx, int H, int KP1, float invKP1)
{
    const int i = blockIdx.x * blockDim.x + threadIdx.x;
    if (i == 0) { g_sum[0] = 0.0; g_sum[1] = 0.0; }
    if (i >= H) return;

    const int r = __ldg(&idx[i]);
    // b = i / KP1 via float reciprocal + exact correction
    int b = __float2int_rz(__int2float_rn(i) * invKP1);
    int k = i - b * KP1;
    if (k < 0)         { b--; k += KP1; }
    else if (k >= KP1) { b++; k -= KP1; }

    const int packed = (b << 13) | k;
    const int pos = atomicAdd(&d_count[r], 1);
    if (pos < CAP) {
        d_ell[(size_t)r * CAP + pos] = packed;
    } else {
        const int o = atomicAdd(&d_ovf_cnt, 1);
        if (o < MAX_OVF) d_ovf[o] = packed;
    }
}

// One warp per bank row; rows in registers; next row prefetched; entries
// processed 4 at a time with the 8-value pack-and-butterfly reduction.
__global__ void __launch_bounds__(256) main_kernel(
        const float4* __restrict__ v1,
        const float4* __restrict__ v2,
        const int*    __restrict__ idx,
        const float4* __restrict__ mem1,
        const float4* __restrict__ mem2,
        float* __restrict__ out,
        float4* __restrict__ outmem1,
        float4* __restrict__ outmem2,
        int N, int H, int KP1)
{
    const int warpsPerBlock = blockDim.x >> 5;
    const int warpInBlock   = threadIdx.x >> 5;
    const int lane          = threadIdx.x & 31;
    const int gwarp         = blockIdx.x * warpsPerBlock + warpInBlock;
    const int totalWarps    = gridDim.x * warpsPerBlock;

    // this lane's result slot: q = bit2(lane)<<2 | bit3(lane)<<1 | bit4(lane)
    const int q  = ((lane >> 4) & 1) | (((lane >> 3) & 1) << 1) | (((lane >> 2) & 1) << 2);
    const int qe = q >> 1;        // entry slot 0..3
    const int qo = q & 1;         // 0 -> out_v1 (addr d2), 1 -> out_v2 (addr H+d2)
    const bool rep = ((lane & 3) == 0);   // representative lane for this q

    float local0 = 0.0f, local1 = 0.0f;

    int r = gwarp;
    float4 m1, m2;
    int cnt = 0;
    if (r < N) {
        m1  = mem1[(size_t)r * 32 + lane];
        m2  = mem2[(size_t)r * 32 + lane];
        cnt = min(d_count[r], CAP);
    }

    while (r < N) {
        const int rn = r + totalWarps;

        // prefetch next row pair + count
        float4 m1n, m2n;
        int cntn = 0;
        if (rn < N) {
            m1n  = mem1[(size_t)rn * 32 + lane];
            m2n  = mem2[(size_t)rn * 32 + lane];
            cntn = min(d_count[rn], CAP);
        }

        // copy-through of current row (evict-first stores)
        __stcs(&outmem1[(size_t)r * 32 + lane], m1);
        __stcs(&outmem2[(size_t)r * 32 + lane], m2);

        // entry loop, 4 entries per iteration
        for (int j = 0; j < cnt; j += 4) {
            const int4 pk = *reinterpret_cast<const int4*>(
                                &d_ell[(size_t)r * CAP + j]);   // uniform 16B load

            float v0, v1p, v2p, v3, v4p, v5, v6, v7;
            {
                // entry 0 (always valid)
                const int b = pk.x >> 13;
                const float4 x1 = __ldg(&v1[(size_t)b * 32 + lane]);
                const float4 x2 = __ldg(&v2[(size_t)b * 32 + lane]);
                v0  = m2.x * x1.x + m2.y * x1.y + m2.z * x1.z + m2.w * x1.w; // s2 -> out_v1
                v1p = m1.x * x2.x + m1.y * x2.y + m1.z * x2.z + m1.w * x2.w; // s1 -> out_v2
            }
            {
                const int b = ((j + 1 < cnt) ? pk.y : pk.x) >> 13;
                const float4 x1 = __ldg(&v1[(size_t)b * 32 + lane]);
                const float4 x2 = __ldg(&v2[(size_t)b * 32 + lane]);
                v2p = m2.x * x1.x + m2.y * x1.y + m2.z * x1.z + m2.w * x1.w;
                v3  = m1.x * x2.x + m1.y * x2.y + m1.z * x2.z + m1.w * x2.w;
            }
            {
                const int b = ((j + 2 < cnt) ? pk.z : pk.x) >> 13;
                const float4 x1 = __ldg(&v1[(size_t)b * 32 + lane]);
                const float4 x2 = __ldg(&v2[(size_t)b * 32 + lane]);
                v4p = m2.x * x1.x + m2.y * x1.y + m2.z * x1.z + m2.w * x1.w;
                v5  = m1.x * x2.x + m1.y * x2.y + m1.z * x2.z + m1.w * x2.w;
            }
            {
                const int b = ((j + 3 < cnt) ? pk.w : pk.x) >> 13;
                const float4 x1 = __ldg(&v1[(size_t)b * 32 + lane]);
                const float4 x2 = __ldg(&v2[(size_t)b * 32 + lane]);
                v6  = m2.x * x1.x + m2.y * x1.y + m2.z * x1.z + m2.w * x1.w;
                v7  = m1.x * x2.x + m1.y * x2.y + m1.z * x2.z + m1.w * x2.w;
            }

            // ---- 8-value pack-and-butterfly reduction: 16 SHFL + 7 SEL ----
            v0  += __shfl_xor_sync(0xffffffffu, v0,  16);
            v1p += __shfl_xor_sync(0xffffffffu, v1p, 16);
            v2p += __shfl_xor_sync(0xffffffffu, v2p, 16);
            v3  += __shfl_xor_sync(0xffffffffu, v3,  16);
            v4p += __shfl_xor_sync(0xffffffffu, v4p, 16);
            v5  += __shfl_xor_sync(0xffffffffu, v5,  16);
            v6  += __shfl_xor_sync(0xffffffffu, v6,  16);
            v7  += __shfl_xor_sync(0xffffffffu, v7,  16);

            float w0 = (lane & 16) ? v1p : v0;
            float w1 = (lane & 16) ? v3  : v2p;
            float w2 = (lane & 16) ? v5  : v4p;
            float w3 = (lane & 16) ? v7  : v6;
            w0 += __shfl_xor_sync(0xffffffffu, w0, 8);
            w1 += __shfl_xor_sync(0xffffffffu, w1, 8);
            w2 += __shfl_xor_sync(0xffffffffu, w2, 8);
            w3 += __shfl_xor_sync(0xffffffffu, w3, 8);

            float u0 = (lane & 8) ? w1 : w0;
            float u1 = (lane & 8) ? w3 : w2;
            u0 += __shfl_xor_sync(0xffffffffu, u0, 4);
            u1 += __shfl_xor_sync(0xffffffffu, u1, 4);

            float t = (lane & 4) ? u1 : u0;
            t += __shfl_xor_sync(0xffffffffu, t, 2);
            t += __shfl_xor_sync(0xffffffffu, t, 1);

            // lane now holds the full sum for slot q; 8 expf in one MUFU pass
            const float ex = __expf(t * T_INV);

            if (rep && (j + qe) < cnt) {
                const int p  = (qe == 0) ? pk.x : (qe == 1) ? pk.y
                             : (qe == 2) ? pk.z : pk.w;
                const int d2 = (p >> 13) * KP1 + (p & 8191);
                __stcs(&out[qo ? (H + d2) : d2], ex);
                if (qo) local1 += ex; else local0 += ex;
            }
        }

        m1 = m1n; m2 = m2n; cnt = cntn; r = rn;
    }

    // overflow entries (expected: none) — direct full-warp gather path
    const int novf = min(d_ovf_cnt, MAX_OVF);
    for (int o = gwarp; o < novf; o += totalWarps) {
        const int p  = d_ovf[o];
        const int b  = p >> 13;
        const int d2 = b * KP1 + (p & 8191);
        const int rr = __ldg(&idx[d2]);

        const float4 a1 = mem1[(size_t)rr * 32 + lane];
        const float4 a2 = mem2[(size_t)rr * 32 + lane];
        const float4 x1 = __ldg(&v1[(size_t)b * 32 + lane]);
        const float4 x2 = __ldg(&v2[(size_t)b * 32 + lane]);

        float s1 = a1.x * x2.x + a1.y * x2.y + a1.z * x2.z + a1.w * x2.w;
        float s2 = a2.x * x1.x + a2.y * x1.y + a2.z * x1.z + a2.w * x1.w;
        #pragma unroll
        for (int qq = 16; qq > 0; qq >>= 1) {
            s1 += __shfl_xor_sync(0xffffffffu, s1, qq);
            s2 += __shfl_xor_sync(0xffffffffu, s2, qq);
        }
        if (lane == 0) {
            const float e2 = __expf(s2 * T_INV);
            const float e1 = __expf(s1 * T_INV);
            __stcs(&out[d2], e2);
            __stcs(&out[H + d2], e1);
            local0 += e2;
            local1 += e1;
        }
    }

    // block reduce -> one double atomic per block per half
    #pragma unroll
    for (int o = 16; o > 0; o >>= 1) {
        local0 += __shfl_xor_sync(0xffffffffu, local0, o);
        local1 += __shfl_xor_sync(0xffffffffu, local1, o);
    }
    __shared__ float sh0[8], sh1[8];
    if (lane == 0) { sh0[warpInBlock] = local0; sh1[warpInBlock] = local1; }
    __syncthreads();
    if (threadIdx.x == 0) {
        float a = 0.0f, b = 0.0f;
        for (int w = 0; w < warpsPerBlock; ++w) { a += sh0[w]; b += sh1[w]; }
        atomicAdd(&g_sum[0], (double)a);
        atomicAdd(&g_sum[1], (double)b);
    }
}

// Epilogue: scale score halves by 1/Z, momentum-update the B rows, and restore
// the zero-state invariant (counts, overflow counter).
__global__ void __launch_bounds__(256) finish_kernel(
        float4* __restrict__ out4,
        int Hv2,   // 2H/4
        int Hv,    // H/4
        int H, long long Nll, int N,
        const float* __restrict__ v1,
        const float* __restrict__ v2,
        const float* __restrict__ mem1,
        const float* __restrict__ mem2,
        const int*   __restrict__ y,
        float* __restrict__ outmem1,
        float* __restrict__ outmem2,
        int scaleBlocks, int B)
{
    const int bx = (int)blockIdx.x;

    if (bx < scaleBlocks) {
        const int i = bx * blockDim.x + threadIdx.x;
        if (i < Hv2) {
            const double s = (i < Hv) ? g_sum[0] : g_sum[1];
            const float scale = (float)((double)H / (s * (double)Nll));
            float4 v = out4[i];
            v.x *= scale; v.y *= scale; v.z *= scale; v.w *= scale;
            out4[i] = v;
        }
        return;
    }

    if (bx < scaleBlocks + B) {
        // momentum update: 2 (row, view) pairs per block
        const int ub    = bx - scaleBlocks;
        const int which = threadIdx.x >> 7;
        const int t     = threadIdx.x & 127;
        const int lane  = threadIdx.x & 31;
        const int w128  = (threadIdx.x >> 5) & 3;

        const float* v      = which ? v2      : v1;
        const float* mem    = which ? mem2    : mem1;
        float*       outmem = which ? outmem2 : outmem1;

        const int row = __ldg(&y[ub]);
        const float u = MOM * mem[(size_t)row * 128 + t] + (1.0f - MOM) * v[(size_t)ub * 128 + t];

        float ss = u * u;
        #pragma unroll
        for (int o = 16; o > 0; o >>= 1)
            ss += __shfl_xor_sync(0xffffffffu, ss, o);

        __shared__ float sh[2][4];
        if (lane == 0) sh[which][w128] = ss;
        __syncthreads();

        const float tot = sh[which][0] + sh[which][1] + sh[which][2] + sh[which][3];
        outmem[(size_t)row * 128 + t] = u * rsqrtf(tot);
        return;
    }

    // zero-state restore (d_count, d_ovf_cnt not read in this kernel)
    const int zb = bx - scaleBlocks - B;
    const int i  = zb * blockDim.x + threadIdx.x;
    if (i < N) d_count[i] = 0;
    if (i == 0) d_ovf_cnt = 0;
}

extern "C" void kernel_launch(void* const* d_in, const int* in_sizes, int n_in,
                              void* d_out, int out_size)
{
    const float* v1   = (const float*)d_in[0];
    const float* v2   = (const float*)d_in[1];
    const int*   idx  = (const int*)  d_in[2];
    const int*   y    = (const int*)  d_in[3];
    const float* mem1 = (const float*)d_in[4];
    const float* mem2 = (const float*)d_in[5];

    const int B   = in_sizes[3];          // 128
    const int D   = in_sizes[0] / B;      // 128
    const int KP1 = in_sizes[2] / B;      // 4097
    const int N   = in_sizes[4] / D;      // 100000
    const int H   = B * KP1;              // 524416
    const int ND  = N * D;                // 12800000

    float* out = (float*)d_out;
    float* outmem1 = out + 2 * (size_t)H;
    float* outmem2 = outmem1 + (size_t)ND;

    const float invKP1 = 1.0f / (float)KP1;

    build_kernel<<<(H + 255) / 256, 256>>>(idx, H, KP1, invKP1);

    main_kernel<<<1998, 256>>>((const float4*)v1, (const float4*)v2, idx,
                               (const float4*)mem1, (const float4*)mem2,
                               out, (float4*)outmem1, (float4*)outmem2,
                               N, H, KP1);

    const int Hv  = H / 4;
    const int Hv2 = 2 * Hv;
    const int scaleBlocks = (Hv2 + 255) / 256;
    const int zeroBlocks  = (N + 255) / 256;
    finish_kernel<<<scaleBlocks + B + zeroBlocks, 256>>>(
        (float4*)d_out, Hv2, Hv, H, (long long)N, N,
        v1, v2, mem1, mem2, y, outmem1, outmem2, scaleBlocks, B);
}